// round 5
// baseline (speedup 1.0000x reference)
#include <cuda_runtime.h>
#include <cuda_bf16.h>
#include <stdint.h>
#include <math.h>

#define NHEADS 12
#define DH     64
#define LW     49
#define CCH    768
#define NWIN   2048
#define MROWS  (NWIN * LW)                 // 100352
#define XTOT   ((size_t)MROWS * CCH)

// ---------------- device-global split planes -------------------------------
__device__ __nv_bfloat16 g_xh[(size_t)MROWS * CCH];
__device__ __nv_bfloat16 g_xl[(size_t)MROWS * CCH];
__device__ __nv_bfloat16 g_sh[(size_t)MROWS * CCH];   // attention out hi
__device__ __nv_bfloat16 g_sl[(size_t)MROWS * CCH];   // attention out lo
__device__ __nv_bfloat16 g_wqh[12 * 4096], g_wkh[12 * 4096];
__device__ __nv_bfloat16 g_wvh[12 * 4096], g_wvl[12 * 4096];
__device__ __nv_bfloat16 g_woh[589824], g_wol[589824];

// ---------------- helpers ---------------------------------------------------
__device__ __forceinline__ void mma_bf16(float c[4], const uint32_t a[4],
                                         uint32_t b0, uint32_t b1) {
    asm volatile(
        "mma.sync.aligned.m16n8k16.row.col.f32.bf16.bf16.f32 "
        "{%0,%1,%2,%3},{%4,%5,%6,%7},{%8,%9},{%0,%1,%2,%3};\n"
        : "+f"(c[0]), "+f"(c[1]), "+f"(c[2]), "+f"(c[3])
        : "r"(a[0]), "r"(a[1]), "r"(a[2]), "r"(a[3]), "r"(b0), "r"(b1));
}

__device__ __forceinline__ void ldsm4(uint32_t r[4], uint32_t saddr) {
    asm volatile("ldmatrix.sync.aligned.m8n8.x4.shared.b16 {%0,%1,%2,%3},[%4];"
                 : "=r"(r[0]), "=r"(r[1]), "=r"(r[2]), "=r"(r[3]) : "r"(saddr));
}

__device__ __forceinline__ void split_bf(float v, __nv_bfloat16& h, __nv_bfloat16& l) {
    h = __float2bfloat16(v);
    l = __float2bfloat16(v - __bfloat162float(h));
}

__device__ __forceinline__ uint32_t packbf(__nv_bfloat16 a, __nv_bfloat16 b) {
    __nv_bfloat162 t; t.x = a; t.y = b;
    return *reinterpret_cast<uint32_t*>(&t);
}

__device__ __forceinline__ void cpa16(uint32_t dst, const void* src) {
    asm volatile("cp.async.cg.shared.global [%0], [%1], 16;" :: "r"(dst), "l"(src));
}
__device__ __forceinline__ void cpa_commit() { asm volatile("cp.async.commit_group;"); }
template<int N> __device__ __forceinline__ void cpa_wait() {
    asm volatile("cp.async.wait_group %0;" :: "n"(N));
}

// ============================================================================
// Prep kernels: one-time fp32 -> split bf16 conversions
// ============================================================================
__global__ void split_x_kernel(const float* __restrict__ x) {
    size_t np = XTOT / 2;
    for (size_t i = blockIdx.x * (size_t)blockDim.x + threadIdx.x; i < np;
         i += (size_t)gridDim.x * blockDim.x) {
        float2 v = ((const float2*)x)[i];
        __nv_bfloat16 h0, l0, h1, l1;
        split_bf(v.x, h0, l0); split_bf(v.y, h1, l1);
        ((uint32_t*)g_xh)[i] = packbf(h0, h1);
        ((uint32_t*)g_xl)[i] = packbf(l0, l1);
    }
}

__global__ void split_w_kernel(const float* __restrict__ Wq, const float* __restrict__ Wk,
                               const float* __restrict__ Wv, const float* __restrict__ Wo) {
    int np = 589824 / 2;
    for (int i = blockIdx.x * blockDim.x + threadIdx.x; i < np;
         i += gridDim.x * blockDim.x) {
        float2 v = ((const float2*)Wo)[i];
        __nv_bfloat16 h0, l0, h1, l1;
        split_bf(v.x, h0, l0); split_bf(v.y, h1, l1);
        ((uint32_t*)g_woh)[i] = packbf(h0, h1);
        ((uint32_t*)g_wol)[i] = packbf(l0, l1);
        if (i < 24576) {
            float2 q = ((const float2*)Wq)[i];
            ((uint32_t*)g_wqh)[i] = packbf(__float2bfloat16(q.x), __float2bfloat16(q.y));
            float2 k = ((const float2*)Wk)[i];
            ((uint32_t*)g_wkh)[i] = packbf(__float2bfloat16(k.x), __float2bfloat16(k.y));
            float2 w = ((const float2*)Wv)[i];
            split_bf(w.x, h0, l0); split_bf(w.y, h1, l1);
            ((uint32_t*)g_wvh)[i] = packbf(h0, h1);
            ((uint32_t*)g_wvl)[i] = packbf(l0, l1);
        }
    }
}

// ============================================================================
// Kernel A: per-(window, head) fused QKV projection + attention.
// 128 threads (4 warps, 2x2 warp grid over 64x64 padded tiles), ldmatrix+mma.
// ============================================================================
#define STBF  72
#define PLANE (64 * STBF)
#define PLB   (PLANE * 2)
#define SMEMB (8 * PLB)

__device__ __forceinline__ void gemm_pass(float acc[2][4][4], uint32_t aBase,
                                          uint32_t bBase, int mbase, int nbase,
                                          int lane) {
    const int r16 = lane & 15;
    const uint32_t kaq = (lane >> 4) * 16;
    #pragma unroll
    for (int kc = 0; kc < 4; ++kc) {
        uint32_t ka = kaq + kc * 32;
        uint32_t a0[4], a1[4], b0[4], b1[4];
        ldsm4(a0, aBase + (mbase + r16) * 144 + ka);
        ldsm4(a1, aBase + (mbase + 16 + r16) * 144 + ka);
        ldsm4(b0, bBase + (nbase + r16) * 144 + ka);
        ldsm4(b1, bBase + (nbase + 16 + r16) * 144 + ka);
        mma_bf16(acc[0][0], a0, b0[0], b0[2]);
        mma_bf16(acc[0][1], a0, b0[1], b0[3]);
        mma_bf16(acc[0][2], a0, b1[0], b1[2]);
        mma_bf16(acc[0][3], a0, b1[1], b1[3]);
        mma_bf16(acc[1][0], a1, b0[0], b0[2]);
        mma_bf16(acc[1][1], a1, b0[1], b0[3]);
        mma_bf16(acc[1][2], a1, b1[0], b1[2]);
        mma_bf16(acc[1][3], a1, b1[1], b1[3]);
    }
}

__global__ void __launch_bounds__(128, 3)
attn_kernel()
{
    extern __shared__ __nv_bfloat16 sm[];
    __nv_bfloat16* xh = sm;
    __nv_bfloat16* xl = sm + PLANE;
    __nv_bfloat16* Wh = sm + 2 * PLANE;     // Wq / Wv-hi / P-hi
    __nv_bfloat16* Wl = sm + 3 * PLANE;     // Wk / Wv-lo / P-lo
    __nv_bfloat16* Qh = sm + 4 * PLANE;
    __nv_bfloat16* Kh = sm + 5 * PLANE;
    __nv_bfloat16* Vh = sm + 6 * PLANE;     // V transposed [d][m]
    __nv_bfloat16* Vl = sm + 7 * PLANE;
    float* Sc = (float*)sm;                 // scores fp32 [64][68], aliases x

    const int tid = threadIdx.x, lane = tid & 31, wid = tid >> 5;
    const int warp_m = wid >> 1, warp_n = wid & 1;
    const int mbase = warp_m * 32, nbase = warp_n * 32;
    const int lr = lane >> 2, lc = lane & 3;

    const int h = blockIdx.x % NHEADS;
    const int n = blockIdx.x / NHEADS;
    const int b = n >> 6, hb = (n >> 3) & 7, wb = n & 7;

    const uint32_t sb = (uint32_t)__cvta_generic_to_shared(sm);
    const uint32_t sXH = sb, sXL = sb + PLB, sWH = sb + 2 * PLB, sWL = sb + 3 * PLB;
    const uint32_t sQH = sb + 4 * PLB, sKH = sb + 5 * PLB;
    const uint32_t sVH = sb + 6 * PLB, sVL = sb + 7 * PLB;

    // ---- stage x planes + Wq/Wk planes ----
    for (int q = tid; q < 1024; q += 128) {
        int p = q >> 9, rem = q & 511, l = rem >> 3, ch = rem & 7;
        uint4 v = make_uint4(0, 0, 0, 0);
        if (l < LW) {
            int i = l / 7, j = l - i * 7;
            size_t off = (((size_t)(b * 56 + hb * 7 + i)) * 56 + (wb * 7 + j)) * CCH
                         + h * DH + ch * 8;
            v = *(const uint4*)((p ? g_xl : g_xh) + off);
        }
        *(uint4*)((p ? xl : xh) + l * STBF + ch * 8) = v;
    }
    for (int q = tid; q < 1024; q += 128) {
        int p = q >> 9, rem = q & 511, e = rem >> 3, ch = rem & 7;
        *(uint4*)((p ? Wl : Wh) + e * STBF + ch * 8) =
            *(const uint4*)((p ? g_wkh : g_wqh) + h * 4096 + e * 64 + ch * 8);
    }
    __syncthreads();

    // ---- merged Q & K projections: shared A fragments, one phase ----
    {
        float aq[2][4][4] = {}, ak[2][4][4] = {};
        const int r16 = lane & 15;
        const uint32_t kaq = (lane >> 4) * 16;
        #pragma unroll
        for (int kc = 0; kc < 4; ++kc) {
            uint32_t ka = kaq + kc * 32;
            uint32_t a0[4], a1[4], bq0[4], bq1[4], bk0[4], bk1[4];
            ldsm4(a0, sXH + (mbase + r16) * 144 + ka);
            ldsm4(a1, sXH + (mbase + 16 + r16) * 144 + ka);
            ldsm4(bq0, sWH + (nbase + r16) * 144 + ka);
            ldsm4(bq1, sWH + (nbase + 16 + r16) * 144 + ka);
            ldsm4(bk0, sWL + (nbase + r16) * 144 + ka);
            ldsm4(bk1, sWL + (nbase + 16 + r16) * 144 + ka);
            mma_bf16(aq[0][0], a0, bq0[0], bq0[2]);
            mma_bf16(aq[0][1], a0, bq0[1], bq0[3]);
            mma_bf16(aq[0][2], a0, bq1[0], bq1[2]);
            mma_bf16(aq[0][3], a0, bq1[1], bq1[3]);
            mma_bf16(aq[1][0], a1, bq0[0], bq0[2]);
            mma_bf16(aq[1][1], a1, bq0[1], bq0[3]);
            mma_bf16(aq[1][2], a1, bq1[0], bq1[2]);
            mma_bf16(aq[1][3], a1, bq1[1], bq1[3]);
            mma_bf16(ak[0][0], a0, bk0[0], bk0[2]);
            mma_bf16(ak[0][1], a0, bk0[1], bk0[3]);
            mma_bf16(ak[0][2], a0, bk1[0], bk1[2]);
            mma_bf16(ak[0][3], a0, bk1[1], bk1[3]);
            mma_bf16(ak[1][0], a1, bk0[0], bk0[2]);
            mma_bf16(ak[1][1], a1, bk0[1], bk0[3]);
            mma_bf16(ak[1][2], a1, bk1[0], bk1[2]);
            mma_bf16(ak[1][3], a1, bk1[1], bk1[3]);
        }
        uint32_t* OQ = (uint32_t*)Qh;
        uint32_t* OK = (uint32_t*)Kh;
        #pragma unroll
        for (int f = 0; f < 2; ++f)
            #pragma unroll
            for (int g = 0; g < 4; ++g) {
                int r = mbase + 16 * f + lr;
                int w = r * 36 + (nbase + 8 * g) / 2 + lc;
                OQ[w] = packbf(__float2bfloat16(aq[f][g][0]), __float2bfloat16(aq[f][g][1]));
                OQ[w + 8 * 36] = packbf(__float2bfloat16(aq[f][g][2]), __float2bfloat16(aq[f][g][3]));
                OK[w] = packbf(__float2bfloat16(ak[f][g][0]), __float2bfloat16(ak[f][g][1]));
                OK[w + 8 * 36] = packbf(__float2bfloat16(ak[f][g][2]), __float2bfloat16(ak[f][g][3]));
            }
    }
    __syncthreads();

    // ---- V = x @ Wv (3-term split), stored transposed hi/lo ----
    for (int q = tid; q < 1024; q += 128) {
        int p = q >> 9, rem = q & 511, e = rem >> 3, ch = rem & 7;
        *(uint4*)((p ? Wl : Wh) + e * STBF + ch * 8) =
            *(const uint4*)((p ? g_wvl : g_wvh) + h * 4096 + e * 64 + ch * 8);
    }
    __syncthreads();
    {
        float acc[2][4][4] = {};
        gemm_pass(acc, sXH, sWH, mbase, nbase, lane);
        gemm_pass(acc, sXH, sWL, mbase, nbase, lane);
        gemm_pass(acc, sXL, sWH, mbase, nbase, lane);
        #pragma unroll
        for (int f = 0; f < 2; ++f)
            #pragma unroll
            for (int g = 0; g < 4; ++g) {
                int r = mbase + 16 * f + lr;
                int c0 = nbase + 8 * g + 2 * lc;
                __nv_bfloat16 hh, ll;
                split_bf(acc[f][g][0], hh, ll);
                Vh[c0 * STBF + r] = hh;           Vl[c0 * STBF + r] = ll;
                split_bf(acc[f][g][1], hh, ll);
                Vh[(c0 + 1) * STBF + r] = hh;     Vl[(c0 + 1) * STBF + r] = ll;
                split_bf(acc[f][g][2], hh, ll);
                Vh[c0 * STBF + r + 8] = hh;       Vl[c0 * STBF + r + 8] = ll;
                split_bf(acc[f][g][3], hh, ll);
                Vh[(c0 + 1) * STBF + r + 8] = hh; Vl[(c0 + 1) * STBF + r + 8] = ll;
            }
    }
    __syncthreads();

    // ---- scores = Qh @ Kh^T, scale + mask -> Sc (aliases x planes) ----
    {
        float acc[2][4][4] = {};
        gemm_pass(acc, sQH, sKH, mbase, nbase, lane);
        #pragma unroll
        for (int f = 0; f < 2; ++f)
            #pragma unroll
            for (int g = 0; g < 4; ++g) {
                int r = mbase + 16 * f + lr;
                int c = nbase + 8 * g + 2 * lc;
                Sc[r * 68 + c]           = (c     < LW) ? acc[f][g][0] * 0.125f : -1e30f;
                Sc[r * 68 + c + 1]       = (c + 1 < LW) ? acc[f][g][1] * 0.125f : -1e30f;
                Sc[(r + 8) * 68 + c]     = (c     < LW) ? acc[f][g][2] * 0.125f : -1e30f;
                Sc[(r + 8) * 68 + c + 1] = (c + 1 < LW) ? acc[f][g][3] * 0.125f : -1e30f;
            }
    }
    __syncthreads();

    // ---- softmax rows 0..48, write P hi/lo (aliases W planes) ----
    if (tid < LW) {
        float* row = Sc + tid * 68;
        float mx = -1e30f;
        #pragma unroll
        for (int m = 0; m < LW; ++m) mx = fmaxf(mx, row[m]);
        float s = 0.f;
        #pragma unroll
        for (int m = 0; m < LW; ++m) { float e = __expf(row[m] - mx); row[m] = e; s += e; }
        float inv = 1.f / s;
        uint32_t* ph = (uint32_t*)(Wh + tid * STBF);
        uint32_t* pl = (uint32_t*)(Wl + tid * STBF);
        #pragma unroll
        for (int mw = 0; mw < 32; ++mw) {
            int m0 = 2 * mw;
            float p0 = (m0     < LW) ? row[m0] * inv     : 0.f;
            float p1 = (m0 + 1 < LW) ? row[m0 + 1] * inv : 0.f;
            __nv_bfloat16 h0, l0, h1, l1;
            split_bf(p0, h0, l0);
            split_bf(p1, h1, l1);
            ph[mw] = packbf(h0, h1);
            pl[mw] = packbf(l0, l1);
        }
    }
    __syncthreads();

    // ---- out = P @ V (3-term), store split bf16 to g_sh/g_sl ----
    {
        float acc[2][4][4] = {};
        gemm_pass(acc, sWH, sVH, mbase, nbase, lane);
        gemm_pass(acc, sWH, sVL, mbase, nbase, lane);
        gemm_pass(acc, sWL, sVH, mbase, nbase, lane);
        #pragma unroll
        for (int f = 0; f < 2; ++f)
            #pragma unroll
            for (int g = 0; g < 4; ++g) {
                int r = mbase + 16 * f + lr;
                int c = nbase + 8 * g + 2 * lc;
                __nv_bfloat16 h0, l0, h1, l1;
                if (r < LW) {
                    size_t off = ((size_t)n * LW + r) * CCH + h * DH + c;
                    split_bf(acc[f][g][0], h0, l0);
                    split_bf(acc[f][g][1], h1, l1);
                    *(uint32_t*)(g_sh + off) = packbf(h0, h1);
                    *(uint32_t*)(g_sl + off) = packbf(l0, l1);
                }
                if (r + 8 < LW) {
                    size_t off = ((size_t)n * LW + r + 8) * CCH + h * DH + c;
                    split_bf(acc[f][g][2], h0, l0);
                    split_bf(acc[f][g][3], h1, l1);
                    *(uint32_t*)(g_sh + off) = packbf(h0, h1);
                    *(uint32_t*)(g_sl + off) = packbf(l0, l1);
                }
            }
    }
}

// ============================================================================
// Kernel B: y = S @ Wo^T + bo, bf16x3, 3-stage cp.async pipeline, ldmatrix.
// Block 128x64, BK=32, 256 threads (8 warps, 4x2 grid of 32x32 warp tiles).
// One __syncthreads per K-iteration.
// ============================================================================
#define PST 40                         // bf16 stride of staged rows (80 B)
#define PSTG_B 30720                   // bytes per stage
#define POAH 0
#define POAL 10240
#define POBH 20480
#define POBL 25600
#define PROJ_SMEM (3 * PSTG_B)         // 92160 B

__device__ __forceinline__ void proj_stage(uint32_t sb, int s, int kt,
                                           int m_base, int n_base, int tid) {
    const uint32_t base = sb + s * PSTG_B;
    #pragma unroll
    for (int c = tid; c < 1024; c += 256) {        // A hi/lo: 128 rows x 4 chunks
        int p = c >> 9, rem = c & 511, row = rem >> 2, ch = rem & 3;
        const __nv_bfloat16* src =
            (p ? g_sl : g_sh) + (size_t)(m_base + row) * CCH + kt + ch * 8;
        cpa16(base + ((p ? POAL : POAH) + (row * PST + ch * 8) * 2), src);
    }
    #pragma unroll
    for (int c = tid; c < 512; c += 256) {         // B hi/lo: 64 rows x 4 chunks
        int p = c >> 8, rem = c & 255, row = rem >> 2, ch = rem & 3;
        const __nv_bfloat16* src =
            (p ? g_wol : g_woh) + (size_t)(n_base + row) * CCH + kt + ch * 8;
        cpa16(base + ((p ? POBL : POBH) + (row * PST + ch * 8) * 2), src);
    }
    cpa_commit();
}

__global__ void __launch_bounds__(256, 2)
proj_kernel(const float* __restrict__ bo, float* __restrict__ y)
{
    extern __shared__ __nv_bfloat16 psm[];
    const int tid = threadIdx.x, lane = tid & 31, wid = tid >> 5;
    const int warp_m = wid >> 1, warp_n = wid & 1;
    const int lr = lane >> 2, lc = lane & 3;
    // n-fastest grid order: Wo slices and A blocks both L2-resident per wave
    const int n_base = (blockIdx.x % 12) * 64;
    const int m_base = (blockIdx.x / 12) * 128;
    const uint32_t sb = (uint32_t)__cvta_generic_to_shared(psm);
    const int r16 = lane & 15;
    const uint32_t kaq = (lane >> 4) * 16;

    float acc[2][4][4] = {};

    auto compute = [&](int s) {
        const uint32_t base = sb + s * PSTG_B;
        const uint32_t aH = base + POAH, aL = base + POAL;
        const uint32_t bH = base + POBH, bL = base + POBL;
        #pragma unroll
        for (int kc = 0; kc < 2; ++kc) {
            uint32_t ka = kaq + kc * 32;
            uint32_t ah0[4], ah1[4], al0[4], al1[4], bh0[4], bh1[4], bl0[4], bl1[4];
            ldsm4(ah0, aH + (warp_m * 32 + r16) * 80 + ka);
            ldsm4(ah1, aH + (warp_m * 32 + 16 + r16) * 80 + ka);
            ldsm4(al0, aL + (warp_m * 32 + r16) * 80 + ka);
            ldsm4(al1, aL + (warp_m * 32 + 16 + r16) * 80 + ka);
            ldsm4(bh0, bH + (warp_n * 32 + r16) * 80 + ka);
            ldsm4(bh1, bH + (warp_n * 32 + 16 + r16) * 80 + ka);
            ldsm4(bl0, bL + (warp_n * 32 + r16) * 80 + ka);
            ldsm4(bl1, bL + (warp_n * 32 + 16 + r16) * 80 + ka);
            mma_bf16(acc[0][0], ah0, bh0[0], bh0[2]);
            mma_bf16(acc[0][0], ah0, bl0[0], bl0[2]);
            mma_bf16(acc[0][0], al0, bh0[0], bh0[2]);
            mma_bf16(acc[0][1], ah0, bh0[1], bh0[3]);
            mma_bf16(acc[0][1], ah0, bl0[1], bl0[3]);
            mma_bf16(acc[0][1], al0, bh0[1], bh0[3]);
            mma_bf16(acc[0][2], ah0, bh1[0], bh1[2]);
            mma_bf16(acc[0][2], ah0, bl1[0], bl1[2]);
            mma_bf16(acc[0][2], al0, bh1[0], bh1[2]);
            mma_bf16(acc[0][3], ah0, bh1[1], bh1[3]);
            mma_bf16(acc[0][3], ah0, bl1[1], bl1[3]);
            mma_bf16(acc[0][3], al0, bh1[1], bh1[3]);
            mma_bf16(acc[1][0], ah1, bh0[0], bh0[2]);
            mma_bf16(acc[1][0], ah1, bl0[0], bl0[2]);
            mma_bf16(acc[1][0], al1, bh0[0], bh0[2]);
            mma_bf16(acc[1][1], ah1, bh0[1], bh0[3]);
            mma_bf16(acc[1][1], ah1, bl0[1], bl0[3]);
            mma_bf16(acc[1][1], al1, bh0[1], bh0[3]);
            mma_bf16(acc[1][2], ah1, bh1[0], bh1[2]);
            mma_bf16(acc[1][2], ah1, bl1[0], bl1[2]);
            mma_bf16(acc[1][2], al1, bh1[0], bh1[2]);
            mma_bf16(acc[1][3], ah1, bh1[1], bh1[3]);
            mma_bf16(acc[1][3], ah1, bl1[1], bl1[3]);
            mma_bf16(acc[1][3], al1, bh1[1], bh1[3]);
        }
    };

    // 3-stage pipeline over 24 K-iterations (BK=32)
    proj_stage(sb, 0, 0, m_base, n_base, tid);
    proj_stage(sb, 1, 32, m_base, n_base, tid);
    #pragma unroll 1
    for (int t = 0; t < 24; ++t) {
        if (t < 22) cpa_wait<1>(); else cpa_wait<0>();
        __syncthreads();
        compute(t % 3);
        if (t + 2 < 24) proj_stage(sb, (t + 2) % 3, (t + 2) * 32, m_base, n_base, tid);
    }

    // epilogue: bias + fp32 store
    #pragma unroll
    for (int g = 0; g < 4; ++g) {
        int c = n_base + warp_n * 32 + 8 * g + 2 * lc;
        float b0 = bo[c], b1 = bo[c + 1];
        #pragma unroll
        for (int f = 0; f < 2; ++f) {
            int r = m_base + warp_m * 32 + 16 * f + lr;
            *(float2*)&y[(size_t)r * CCH + c] =
                make_float2(acc[f][g][0] + b0, acc[f][g][1] + b1);
            *(float2*)&y[(size_t)(r + 8) * CCH + c] =
                make_float2(acc[f][g][2] + b0, acc[f][g][3] + b1);
        }
    }
}

// ============================================================================
extern "C" void kernel_launch(void* const* d_in, const int* in_sizes, int n_in,
                              void* d_out, int out_size)
{
    const float* x  = (const float*)d_in[0];
    const float* Wq = (const float*)d_in[1];
    const float* Wk = (const float*)d_in[2];
    const float* Wv = (const float*)d_in[3];
    const float* Wo = (const float*)d_in[4];
    const float* bo = (const float*)d_in[5];
    float* y = (float*)d_out;

    cudaFuncSetAttribute(attn_kernel, cudaFuncAttributeMaxDynamicSharedMemorySize, SMEMB);
    cudaFuncSetAttribute(proj_kernel, cudaFuncAttributeMaxDynamicSharedMemorySize, PROJ_SMEM);

    split_x_kernel<<<2048, 256>>>(x);
    split_w_kernel<<<576, 256>>>(Wq, Wk, Wv, Wo);
    attn_kernel<<<NWIN * NHEADS, 128, SMEMB>>>();
    proj_kernel<<<784 * 12, 256, PROJ_SMEM>>>(bo, y);
}

// round 6
// speedup vs baseline: 1.0784x; 1.0784x over previous
#include <cuda_runtime.h>
#include <cuda_bf16.h>
#include <stdint.h>
#include <math.h>

#define NHEADS 12
#define DH     64
#define LW     49
#define CCH    768
#define NWIN   2048
#define MROWS  (NWIN * LW)                 // 100352
#define XTOT   ((size_t)MROWS * CCH)

// ---------------- device-global split planes -------------------------------
__device__ __nv_bfloat16 g_xh[(size_t)MROWS * CCH];
__device__ __nv_bfloat16 g_xl[(size_t)MROWS * CCH];
__device__ __nv_bfloat16 g_sh[(size_t)MROWS * CCH];   // attention out hi
__device__ __nv_bfloat16 g_sl[(size_t)MROWS * CCH];   // attention out lo
__device__ __nv_bfloat16 g_wqh[12 * 4096], g_wkh[12 * 4096];
__device__ __nv_bfloat16 g_wvh[12 * 4096], g_wvl[12 * 4096];
__device__ __nv_bfloat16 g_woh[589824], g_wol[589824];

// ---------------- helpers ---------------------------------------------------
__device__ __forceinline__ void mma_bf16(float c[4], const uint32_t a[4],
                                         uint32_t b0, uint32_t b1) {
    asm volatile(
        "mma.sync.aligned.m16n8k16.row.col.f32.bf16.bf16.f32 "
        "{%0,%1,%2,%3},{%4,%5,%6,%7},{%8,%9},{%0,%1,%2,%3};\n"
        : "+f"(c[0]), "+f"(c[1]), "+f"(c[2]), "+f"(c[3])
        : "r"(a[0]), "r"(a[1]), "r"(a[2]), "r"(a[3]), "r"(b0), "r"(b1));
}

__device__ __forceinline__ void ldsm4(uint32_t r[4], uint32_t saddr) {
    asm volatile("ldmatrix.sync.aligned.m8n8.x4.shared.b16 {%0,%1,%2,%3},[%4];"
                 : "=r"(r[0]), "=r"(r[1]), "=r"(r[2]), "=r"(r[3]) : "r"(saddr));
}

__device__ __forceinline__ void split_bf(float v, __nv_bfloat16& h, __nv_bfloat16& l) {
    h = __float2bfloat16(v);
    l = __float2bfloat16(v - __bfloat162float(h));
}

__device__ __forceinline__ uint32_t packbf(__nv_bfloat16 a, __nv_bfloat16 b) {
    __nv_bfloat162 t; t.x = a; t.y = b;
    return *reinterpret_cast<uint32_t*>(&t);
}

__device__ __forceinline__ void cpa16(uint32_t dst, const void* src) {
    asm volatile("cp.async.cg.shared.global [%0], [%1], 16;" :: "r"(dst), "l"(src));
}
__device__ __forceinline__ void cpa_commit() { asm volatile("cp.async.commit_group;"); }
template<int N> __device__ __forceinline__ void cpa_wait() {
    asm volatile("cp.async.wait_group %0;" :: "n"(N));
}

// ============================================================================
// Prep kernels: one-time fp32 -> split bf16 conversions
// ============================================================================
__global__ void split_x_kernel(const float* __restrict__ x) {
    size_t np = XTOT / 2;
    for (size_t i = blockIdx.x * (size_t)blockDim.x + threadIdx.x; i < np;
         i += (size_t)gridDim.x * blockDim.x) {
        float2 v = ((const float2*)x)[i];
        __nv_bfloat16 h0, l0, h1, l1;
        split_bf(v.x, h0, l0); split_bf(v.y, h1, l1);
        ((uint32_t*)g_xh)[i] = packbf(h0, h1);
        ((uint32_t*)g_xl)[i] = packbf(l0, l1);
    }
}

__global__ void split_w_kernel(const float* __restrict__ Wq, const float* __restrict__ Wk,
                               const float* __restrict__ Wv, const float* __restrict__ Wo) {
    int np = 589824 / 2;
    for (int i = blockIdx.x * blockDim.x + threadIdx.x; i < np;
         i += gridDim.x * blockDim.x) {
        float2 v = ((const float2*)Wo)[i];
        __nv_bfloat16 h0, l0, h1, l1;
        split_bf(v.x, h0, l0); split_bf(v.y, h1, l1);
        ((uint32_t*)g_woh)[i] = packbf(h0, h1);
        ((uint32_t*)g_wol)[i] = packbf(l0, l1);
        if (i < 24576) {
            float2 q = ((const float2*)Wq)[i];
            ((uint32_t*)g_wqh)[i] = packbf(__float2bfloat16(q.x), __float2bfloat16(q.y));
            float2 k = ((const float2*)Wk)[i];
            ((uint32_t*)g_wkh)[i] = packbf(__float2bfloat16(k.x), __float2bfloat16(k.y));
            float2 w = ((const float2*)Wv)[i];
            split_bf(w.x, h0, l0); split_bf(w.y, h1, l1);
            ((uint32_t*)g_wvh)[i] = packbf(h0, h1);
            ((uint32_t*)g_wvl)[i] = packbf(l0, l1);
        }
    }
}

// ============================================================================
// Kernel A: per-(window, head) fused QKV projection + attention.
// 128 threads (4 warps, 2x2 warp grid over 64x64 padded tiles), ldmatrix+mma.
// ============================================================================
#define STBF  72
#define PLANE (64 * STBF)
#define PLB   (PLANE * 2)
#define SMEMB (8 * PLB)
#define SCST  65                       // fp32 score-row stride (conflict-free)

__device__ __forceinline__ void gemm_pass(float acc[2][4][4], uint32_t aBase,
                                          uint32_t bBase, int mbase, int nbase,
                                          int lane) {
    const int r16 = lane & 15;
    const uint32_t kaq = (lane >> 4) * 16;
    #pragma unroll
    for (int kc = 0; kc < 4; ++kc) {
        uint32_t ka = kaq + kc * 32;
        uint32_t a0[4], a1[4], b0[4], b1[4];
        ldsm4(a0, aBase + (mbase + r16) * 144 + ka);
        ldsm4(a1, aBase + (mbase + 16 + r16) * 144 + ka);
        ldsm4(b0, bBase + (nbase + r16) * 144 + ka);
        ldsm4(b1, bBase + (nbase + 16 + r16) * 144 + ka);
        mma_bf16(acc[0][0], a0, b0[0], b0[2]);
        mma_bf16(acc[0][1], a0, b0[1], b0[3]);
        mma_bf16(acc[0][2], a0, b1[0], b1[2]);
        mma_bf16(acc[0][3], a0, b1[1], b1[3]);
        mma_bf16(acc[1][0], a1, b0[0], b0[2]);
        mma_bf16(acc[1][1], a1, b0[1], b0[3]);
        mma_bf16(acc[1][2], a1, b1[0], b1[2]);
        mma_bf16(acc[1][3], a1, b1[1], b1[3]);
    }
}

__global__ void __launch_bounds__(128, 3)
attn_kernel()
{
    extern __shared__ __nv_bfloat16 sm[];
    __nv_bfloat16* xh = sm;
    __nv_bfloat16* xl = sm + PLANE;
    __nv_bfloat16* Wh = sm + 2 * PLANE;     // Wq / Wv-hi / P-hi
    __nv_bfloat16* Wl = sm + 3 * PLANE;     // Wk / Wv-lo / P-lo
    __nv_bfloat16* Qh = sm + 4 * PLANE;
    __nv_bfloat16* Kh = sm + 5 * PLANE;
    __nv_bfloat16* Vh = sm + 6 * PLANE;     // V transposed [d][m]
    __nv_bfloat16* Vl = sm + 7 * PLANE;
    float* Sc = (float*)sm;                 // scores fp32 [64][65], aliases x

    const int tid = threadIdx.x, lane = tid & 31, wid = tid >> 5;
    const int warp_m = wid >> 1, warp_n = wid & 1;
    const int mbase = warp_m * 32, nbase = warp_n * 32;
    const int lr = lane >> 2, lc = lane & 3;

    const int h = blockIdx.x % NHEADS;
    const int n = blockIdx.x / NHEADS;
    const int b = n >> 6, hb = (n >> 3) & 7, wb = n & 7;

    const uint32_t sb = (uint32_t)__cvta_generic_to_shared(sm);
    const uint32_t sXH = sb, sXL = sb + PLB, sWH = sb + 2 * PLB, sWL = sb + 3 * PLB;
    const uint32_t sQH = sb + 4 * PLB, sKH = sb + 5 * PLB;
    const uint32_t sVH = sb + 6 * PLB, sVL = sb + 7 * PLB;

    // ---- stage x planes + Wq/Wk planes ----
    for (int q = tid; q < 1024; q += 128) {
        int p = q >> 9, rem = q & 511, l = rem >> 3, ch = rem & 7;
        uint4 v = make_uint4(0, 0, 0, 0);
        if (l < LW) {
            int i = l / 7, j = l - i * 7;
            size_t off = (((size_t)(b * 56 + hb * 7 + i)) * 56 + (wb * 7 + j)) * CCH
                         + h * DH + ch * 8;
            v = *(const uint4*)((p ? g_xl : g_xh) + off);
        }
        *(uint4*)((p ? xl : xh) + l * STBF + ch * 8) = v;
    }
    for (int q = tid; q < 1024; q += 128) {
        int p = q >> 9, rem = q & 511, e = rem >> 3, ch = rem & 7;
        *(uint4*)((p ? Wl : Wh) + e * STBF + ch * 8) =
            *(const uint4*)((p ? g_wkh : g_wqh) + h * 4096 + e * 64 + ch * 8);
    }
    __syncthreads();

    // ---- merged Q & K projections: shared A fragments, one phase ----
    {
        float aq[2][4][4] = {}, ak[2][4][4] = {};
        const int r16 = lane & 15;
        const uint32_t kaq = (lane >> 4) * 16;
        #pragma unroll
        for (int kc = 0; kc < 4; ++kc) {
            uint32_t ka = kaq + kc * 32;
            uint32_t a0[4], a1[4], bq0[4], bq1[4], bk0[4], bk1[4];
            ldsm4(a0, sXH + (mbase + r16) * 144 + ka);
            ldsm4(a1, sXH + (mbase + 16 + r16) * 144 + ka);
            ldsm4(bq0, sWH + (nbase + r16) * 144 + ka);
            ldsm4(bq1, sWH + (nbase + 16 + r16) * 144 + ka);
            ldsm4(bk0, sWL + (nbase + r16) * 144 + ka);
            ldsm4(bk1, sWL + (nbase + 16 + r16) * 144 + ka);
            mma_bf16(aq[0][0], a0, bq0[0], bq0[2]);
            mma_bf16(aq[0][1], a0, bq0[1], bq0[3]);
            mma_bf16(aq[0][2], a0, bq1[0], bq1[2]);
            mma_bf16(aq[0][3], a0, bq1[1], bq1[3]);
            mma_bf16(aq[1][0], a1, bq0[0], bq0[2]);
            mma_bf16(aq[1][1], a1, bq0[1], bq0[3]);
            mma_bf16(aq[1][2], a1, bq1[0], bq1[2]);
            mma_bf16(aq[1][3], a1, bq1[1], bq1[3]);
            mma_bf16(ak[0][0], a0, bk0[0], bk0[2]);
            mma_bf16(ak[0][1], a0, bk0[1], bk0[3]);
            mma_bf16(ak[0][2], a0, bk1[0], bk1[2]);
            mma_bf16(ak[0][3], a0, bk1[1], bk1[3]);
            mma_bf16(ak[1][0], a1, bk0[0], bk0[2]);
            mma_bf16(ak[1][1], a1, bk0[1], bk0[3]);
            mma_bf16(ak[1][2], a1, bk1[0], bk1[2]);
            mma_bf16(ak[1][3], a1, bk1[1], bk1[3]);
        }
        uint32_t* OQ = (uint32_t*)Qh;
        uint32_t* OK = (uint32_t*)Kh;
        #pragma unroll
        for (int f = 0; f < 2; ++f)
            #pragma unroll
            for (int g = 0; g < 4; ++g) {
                int r = mbase + 16 * f + lr;
                int w = r * 36 + (nbase + 8 * g) / 2 + lc;
                OQ[w] = packbf(__float2bfloat16(aq[f][g][0]), __float2bfloat16(aq[f][g][1]));
                OQ[w + 8 * 36] = packbf(__float2bfloat16(aq[f][g][2]), __float2bfloat16(aq[f][g][3]));
                OK[w] = packbf(__float2bfloat16(ak[f][g][0]), __float2bfloat16(ak[f][g][1]));
                OK[w + 8 * 36] = packbf(__float2bfloat16(ak[f][g][2]), __float2bfloat16(ak[f][g][3]));
            }
    }
    __syncthreads();

    // ---- V = x @ Wv (3-term split), stored transposed hi/lo ----
    for (int q = tid; q < 1024; q += 128) {
        int p = q >> 9, rem = q & 511, e = rem >> 3, ch = rem & 7;
        *(uint4*)((p ? Wl : Wh) + e * STBF + ch * 8) =
            *(const uint4*)((p ? g_wvl : g_wvh) + h * 4096 + e * 64 + ch * 8);
    }
    __syncthreads();
    {
        float acc[2][4][4] = {};
        gemm_pass(acc, sXH, sWH, mbase, nbase, lane);
        gemm_pass(acc, sXH, sWL, mbase, nbase, lane);
        gemm_pass(acc, sXL, sWH, mbase, nbase, lane);
        #pragma unroll
        for (int f = 0; f < 2; ++f)
            #pragma unroll
            for (int g = 0; g < 4; ++g) {
                int r = mbase + 16 * f + lr;
                int c0 = nbase + 8 * g + 2 * lc;
                __nv_bfloat16 hh, ll;
                split_bf(acc[f][g][0], hh, ll);
                Vh[c0 * STBF + r] = hh;           Vl[c0 * STBF + r] = ll;
                split_bf(acc[f][g][1], hh, ll);
                Vh[(c0 + 1) * STBF + r] = hh;     Vl[(c0 + 1) * STBF + r] = ll;
                split_bf(acc[f][g][2], hh, ll);
                Vh[c0 * STBF + r + 8] = hh;       Vl[c0 * STBF + r + 8] = ll;
                split_bf(acc[f][g][3], hh, ll);
                Vh[(c0 + 1) * STBF + r + 8] = hh; Vl[(c0 + 1) * STBF + r + 8] = ll;
            }
    }
    __syncthreads();

    // ---- scores = Qh @ Kh^T, scale + mask -> Sc (aliases x planes) ----
    {
        float acc[2][4][4] = {};
        gemm_pass(acc, sQH, sKH, mbase, nbase, lane);
        #pragma unroll
        for (int f = 0; f < 2; ++f)
            #pragma unroll
            for (int g = 0; g < 4; ++g) {
                int r = mbase + 16 * f + lr;
                int c = nbase + 8 * g + 2 * lc;
                Sc[r * SCST + c]           = (c     < LW) ? acc[f][g][0] * 0.125f : -1e30f;
                Sc[r * SCST + c + 1]       = (c + 1 < LW) ? acc[f][g][1] * 0.125f : -1e30f;
                Sc[(r + 8) * SCST + c]     = (c     < LW) ? acc[f][g][2] * 0.125f : -1e30f;
                Sc[(r + 8) * SCST + c + 1] = (c + 1 < LW) ? acc[f][g][3] * 0.125f : -1e30f;
            }
    }
    __syncthreads();

    // ---- softmax rows 0..48, write P hi/lo (aliases W planes) ----
    if (tid < LW) {
        float* row = Sc + tid * SCST;
        float mx = -1e30f;
        #pragma unroll
        for (int m = 0; m < LW; ++m) mx = fmaxf(mx, row[m]);
        float s = 0.f;
        #pragma unroll
        for (int m = 0; m < LW; ++m) { float e = __expf(row[m] - mx); row[m] = e; s += e; }
        float inv = 1.f / s;
        uint32_t* ph = (uint32_t*)(Wh + tid * STBF);
        uint32_t* pl = (uint32_t*)(Wl + tid * STBF);
        #pragma unroll
        for (int mw = 0; mw < 32; ++mw) {
            int m0 = 2 * mw;
            float p0 = (m0     < LW) ? row[m0] * inv     : 0.f;
            float p1 = (m0 + 1 < LW) ? row[m0 + 1] * inv : 0.f;
            __nv_bfloat16 h0, l0, h1, l1;
            split_bf(p0, h0, l0);
            split_bf(p1, h1, l1);
            ph[mw] = packbf(h0, h1);
            pl[mw] = packbf(l0, l1);
        }
    }
    __syncthreads();

    // ---- out = P @ V (3-term), store split bf16 to g_sh/g_sl ----
    {
        float acc[2][4][4] = {};
        gemm_pass(acc, sWH, sVH, mbase, nbase, lane);
        gemm_pass(acc, sWH, sVL, mbase, nbase, lane);
        gemm_pass(acc, sWL, sVH, mbase, nbase, lane);
        #pragma unroll
        for (int f = 0; f < 2; ++f)
            #pragma unroll
            for (int g = 0; g < 4; ++g) {
                int r = mbase + 16 * f + lr;
                int c = nbase + 8 * g + 2 * lc;
                __nv_bfloat16 h0, l0, h1, l1;
                if (r < LW) {
                    size_t off = ((size_t)n * LW + r) * CCH + h * DH + c;
                    split_bf(acc[f][g][0], h0, l0);
                    split_bf(acc[f][g][1], h1, l1);
                    *(uint32_t*)(g_sh + off) = packbf(h0, h1);
                    *(uint32_t*)(g_sl + off) = packbf(l0, l1);
                }
                if (r + 8 < LW) {
                    size_t off = ((size_t)n * LW + r + 8) * CCH + h * DH + c;
                    split_bf(acc[f][g][2], h0, l0);
                    split_bf(acc[f][g][3], h1, l1);
                    *(uint32_t*)(g_sh + off) = packbf(h0, h1);
                    *(uint32_t*)(g_sl + off) = packbf(l0, l1);
                }
            }
    }
}

// ============================================================================
// Kernel B: y = S @ Wo^T + bo, bf16x3, 3-stage cp.async pipeline, SWIZZLED
// unpadded 64B rows (24576 B/stage -> 3 CTAs/SM AND one barrier per iter).
// Block 128x64, BK=32, 256 threads (8 warps, 4x2 grid of 32x32 warp tiles).
// ============================================================================
#define PSTG 24576                     // bytes per stage
#define QAH  0                         // A hi: 128 rows x 64 B
#define QAL  8192                      // A lo
#define QBH  16384                     // B hi: 64 rows x 64 B
#define QBL  20480                     // B lo
#define PROJ_SMEM (3 * PSTG)           // 73728 B

// swizzled byte offset of 16B chunk `ch` (0..3) in row `row` (64 B rows)
__device__ __forceinline__ uint32_t swr(int row, int ch) {
    return (uint32_t)(row * 64 + ((ch ^ ((row >> 1) & 3)) << 4));
}

__device__ __forceinline__ void proj_stage(uint32_t sb, int s, int kt,
                                           int m_base, int n_base, int tid) {
    const uint32_t base = sb + s * PSTG;
    #pragma unroll
    for (int c = tid; c < 1024; c += 256) {        // A hi/lo: 128 rows x 4 chunks
        int p = c >> 9, rem = c & 511, row = rem >> 2, ch = rem & 3;
        const __nv_bfloat16* src =
            (p ? g_sl : g_sh) + (size_t)(m_base + row) * CCH + kt + ch * 8;
        cpa16(base + (p ? QAL : QAH) + swr(row, ch), src);
    }
    #pragma unroll
    for (int c = tid; c < 512; c += 256) {         // B hi/lo: 64 rows x 4 chunks
        int p = c >> 8, rem = c & 255, row = rem >> 2, ch = rem & 3;
        const __nv_bfloat16* src =
            (p ? g_wol : g_woh) + (size_t)(n_base + row) * CCH + kt + ch * 8;
        cpa16(base + (p ? QBL : QBH) + swr(row, ch), src);
    }
    cpa_commit();
}

__global__ void __launch_bounds__(256, 3)
proj_kernel(const float* __restrict__ bo, float* __restrict__ y)
{
    extern __shared__ __nv_bfloat16 psm[];
    const int tid = threadIdx.x, lane = tid & 31, wid = tid >> 5;
    const int warp_m = wid >> 1, warp_n = wid & 1;
    const int lr = lane >> 2, lc = lane & 3;
    // n-fastest grid order: Wo slices and A blocks both L2-resident per wave
    const int n_base = (blockIdx.x % 12) * 64;
    const int m_base = (blockIdx.x / 12) * 128;
    const uint32_t sb = (uint32_t)__cvta_generic_to_shared(psm);
    const int r16 = lane & 15;
    const int colq = (lane >> 4);      // 16B-chunk column half (0/1)

    float acc[2][4][4] = {};

    auto compute = [&](int s) {
        const uint32_t base = sb + s * PSTG;
        const uint32_t aH = base + QAH, aL = base + QAL;
        const uint32_t bH = base + QBH, bL = base + QBL;
        #pragma unroll
        for (int kc = 0; kc < 2; ++kc) {
            const int ch = colq + kc * 2;          // 16B chunk index 0..3
            const int ra0 = warp_m * 32 + r16, ra1 = ra0 + 16;
            const int rb0 = warp_n * 32 + r16, rb1 = rb0 + 16;
            uint32_t ah0[4], ah1[4], al0[4], al1[4], bh0[4], bh1[4], bl0[4], bl1[4];
            ldsm4(ah0, aH + swr(ra0, ch));
            ldsm4(ah1, aH + swr(ra1, ch));
            ldsm4(al0, aL + swr(ra0, ch));
            ldsm4(al1, aL + swr(ra1, ch));
            ldsm4(bh0, bH + swr(rb0, ch));
            ldsm4(bh1, bH + swr(rb1, ch));
            ldsm4(bl0, bL + swr(rb0, ch));
            ldsm4(bl1, bL + swr(rb1, ch));
            mma_bf16(acc[0][0], ah0, bh0[0], bh0[2]);
            mma_bf16(acc[0][0], ah0, bl0[0], bl0[2]);
            mma_bf16(acc[0][0], al0, bh0[0], bh0[2]);
            mma_bf16(acc[0][1], ah0, bh0[1], bh0[3]);
            mma_bf16(acc[0][1], ah0, bl0[1], bl0[3]);
            mma_bf16(acc[0][1], al0, bh0[1], bh0[3]);
            mma_bf16(acc[0][2], ah0, bh1[0], bh1[2]);
            mma_bf16(acc[0][2], ah0, bl1[0], bl1[2]);
            mma_bf16(acc[0][2], al0, bh1[0], bh1[2]);
            mma_bf16(acc[0][3], ah0, bh1[1], bh1[3]);
            mma_bf16(acc[0][3], ah0, bl1[1], bl1[3]);
            mma_bf16(acc[0][3], al0, bh1[1], bh1[3]);
            mma_bf16(acc[1][0], ah1, bh0[0], bh0[2]);
            mma_bf16(acc[1][0], ah1, bl0[0], bl0[2]);
            mma_bf16(acc[1][0], al1, bh0[0], bh0[2]);
            mma_bf16(acc[1][1], ah1, bh0[1], bh0[3]);
            mma_bf16(acc[1][1], ah1, bl0[1], bl0[3]);
            mma_bf16(acc[1][1], al1, bh0[1], bh0[3]);
            mma_bf16(acc[1][2], ah1, bh1[0], bh1[2]);
            mma_bf16(acc[1][2], ah1, bl1[0], bl1[2]);
            mma_bf16(acc[1][2], al1, bh1[0], bh1[2]);
            mma_bf16(acc[1][3], ah1, bh1[1], bh1[3]);
            mma_bf16(acc[1][3], ah1, bl1[1], bl1[3]);
            mma_bf16(acc[1][3], al1, bh1[1], bh1[3]);
        }
    };

    // 3-stage pipeline over 24 K-iterations (BK=32), ONE barrier per iter.
    // Hazard: stage(t+2) writes buf (t+2)%3; last reader of that buf was
    // compute(t-1), ordered by the barrier inside iteration t.
    proj_stage(sb, 0, 0, m_base, n_base, tid);
    proj_stage(sb, 1, 32, m_base, n_base, tid);
    #pragma unroll 1
    for (int t = 0; t < 24; ++t) {
        if (t < 23) cpa_wait<1>(); else cpa_wait<0>();
        __syncthreads();
        compute(t % 3);
        if (t + 2 < 24) proj_stage(sb, (t + 2) % 3, (t + 2) * 32, m_base, n_base, tid);
    }

    // epilogue: bias + fp32 store
    #pragma unroll
    for (int g = 0; g < 4; ++g) {
        int c = n_base + warp_n * 32 + 8 * g + 2 * lc;
        float b0 = bo[c], b1 = bo[c + 1];
        #pragma unroll
        for (int f = 0; f < 2; ++f) {
            int r = m_base + warp_m * 32 + 16 * f + lr;
            *(float2*)&y[(size_t)r * CCH + c] =
                make_float2(acc[f][g][0] + b0, acc[f][g][1] + b1);
            *(float2*)&y[(size_t)(r + 8) * CCH + c] =
                make_float2(acc[f][g][2] + b0, acc[f][g][3] + b1);
        }
    }
}

// ============================================================================
extern "C" void kernel_launch(void* const* d_in, const int* in_sizes, int n_in,
                              void* d_out, int out_size)
{
    const float* x  = (const float*)d_in[0];
    const float* Wq = (const float*)d_in[1];
    const float* Wk = (const float*)d_in[2];
    const float* Wv = (const float*)d_in[3];
    const float* Wo = (const float*)d_in[4];
    const float* bo = (const float*)d_in[5];
    float* y = (float*)d_out;

    cudaFuncSetAttribute(attn_kernel, cudaFuncAttributeMaxDynamicSharedMemorySize, SMEMB);
    cudaFuncSetAttribute(proj_kernel, cudaFuncAttributeMaxDynamicSharedMemorySize, PROJ_SMEM);

    split_x_kernel<<<2048, 256>>>(x);
    split_w_kernel<<<576, 256>>>(Wq, Wk, Wv, Wo);
    attn_kernel<<<NWIN * NHEADS, 128, SMEMB>>>();
    proj_kernel<<<784 * 12, 256, PROJ_SMEM>>>(bo, y);
}

// round 7
// speedup vs baseline: 1.2060x; 1.1184x over previous
#include <cuda_runtime.h>
#include <cuda_bf16.h>
#include <stdint.h>
#include <math.h>

#define NHEADS 12
#define DH     64
#define LW     49
#define CCH    768
#define NWIN   2048
#define MROWS  (NWIN * LW)                 // 100352
#define XTOT   ((size_t)MROWS * CCH)

// ---------------- device-global split planes -------------------------------
__device__ __nv_bfloat16 g_sh[(size_t)MROWS * CCH];   // attention out hi
__device__ __nv_bfloat16 g_sl[(size_t)MROWS * CCH];   // attention out lo
__device__ __nv_bfloat16 g_wqh[12 * 4096], g_wkh[12 * 4096];
__device__ __nv_bfloat16 g_wvh[12 * 4096], g_wvl[12 * 4096];
__device__ __nv_bfloat16 g_woh[589824], g_wol[589824];

// ---------------- helpers ---------------------------------------------------
__device__ __forceinline__ void mma_bf16(float c[4], const uint32_t a[4],
                                         uint32_t b0, uint32_t b1) {
    asm volatile(
        "mma.sync.aligned.m16n8k16.row.col.f32.bf16.bf16.f32 "
        "{%0,%1,%2,%3},{%4,%5,%6,%7},{%8,%9},{%0,%1,%2,%3};\n"
        : "+f"(c[0]), "+f"(c[1]), "+f"(c[2]), "+f"(c[3])
        : "r"(a[0]), "r"(a[1]), "r"(a[2]), "r"(a[3]), "r"(b0), "r"(b1));
}

__device__ __forceinline__ void ldsm4(uint32_t r[4], uint32_t saddr) {
    asm volatile("ldmatrix.sync.aligned.m8n8.x4.shared.b16 {%0,%1,%2,%3},[%4];"
                 : "=r"(r[0]), "=r"(r[1]), "=r"(r[2]), "=r"(r[3]) : "r"(saddr));
}

__device__ __forceinline__ void ldsm4t(uint32_t r[4], uint32_t saddr) {
    asm volatile("ldmatrix.sync.aligned.m8n8.x4.trans.shared.b16 {%0,%1,%2,%3},[%4];"
                 : "=r"(r[0]), "=r"(r[1]), "=r"(r[2]), "=r"(r[3]) : "r"(saddr));
}

__device__ __forceinline__ void split_bf(float v, __nv_bfloat16& h, __nv_bfloat16& l) {
    h = __float2bfloat16(v);
    l = __float2bfloat16(v - __bfloat162float(h));
}

__device__ __forceinline__ uint32_t packbf(__nv_bfloat16 a, __nv_bfloat16 b) {
    __nv_bfloat162 t; t.x = a; t.y = b;
    return *reinterpret_cast<uint32_t*>(&t);
}

__device__ __forceinline__ void cpa16(uint32_t dst, const void* src) {
    asm volatile("cp.async.cg.shared.global [%0], [%1], 16;" :: "r"(dst), "l"(src));
}
__device__ __forceinline__ void cpa_commit() { asm volatile("cp.async.commit_group;"); }
template<int N> __device__ __forceinline__ void cpa_wait() {
    asm volatile("cp.async.wait_group %0;" :: "n"(N));
}

// ============================================================================
// Prep: weights only (x is split inline inside attn now)
// ============================================================================
__global__ void split_w_kernel(const float* __restrict__ Wq, const float* __restrict__ Wk,
                               const float* __restrict__ Wv, const float* __restrict__ Wo) {
    int np = 589824 / 2;
    for (int i = blockIdx.x * blockDim.x + threadIdx.x; i < np;
         i += gridDim.x * blockDim.x) {
        float2 v = ((const float2*)Wo)[i];
        __nv_bfloat16 h0, l0, h1, l1;
        split_bf(v.x, h0, l0); split_bf(v.y, h1, l1);
        ((uint32_t*)g_woh)[i] = packbf(h0, h1);
        ((uint32_t*)g_wol)[i] = packbf(l0, l1);
        if (i < 24576) {
            float2 q = ((const float2*)Wq)[i];
            ((uint32_t*)g_wqh)[i] = packbf(__float2bfloat16(q.x), __float2bfloat16(q.y));
            float2 k = ((const float2*)Wk)[i];
            ((uint32_t*)g_wkh)[i] = packbf(__float2bfloat16(k.x), __float2bfloat16(k.y));
            float2 w = ((const float2*)Wv)[i];
            split_bf(w.x, h0, l0); split_bf(w.y, h1, l1);
            ((uint32_t*)g_wvh)[i] = packbf(h0, h1);
            ((uint32_t*)g_wvl)[i] = packbf(l0, l1);
        }
    }
}

// ============================================================================
// Kernel A: per-(window, head) fused QKV projection + attention.
// 128 threads (4 warps, 2x2 warp grid over 64x64 padded tiles), ldmatrix+mma.
// ============================================================================
#define STBF  72
#define PLANE (64 * STBF)
#define PLB   (PLANE * 2)
#define SMEMB (8 * PLB)
#define SCST  65                       // fp32 score-row stride (conflict-free)

__device__ __forceinline__ void gemm_pass(float acc[2][4][4], uint32_t aBase,
                                          uint32_t bBase, int mbase, int nbase,
                                          int lane) {
    const int r16 = lane & 15;
    const uint32_t kaq = (lane >> 4) * 16;
    #pragma unroll
    for (int kc = 0; kc < 4; ++kc) {
        uint32_t ka = kaq + kc * 32;
        uint32_t a0[4], a1[4], b0[4], b1[4];
        ldsm4(a0, aBase + (mbase + r16) * 144 + ka);
        ldsm4(a1, aBase + (mbase + 16 + r16) * 144 + ka);
        ldsm4(b0, bBase + (nbase + r16) * 144 + ka);
        ldsm4(b1, bBase + (nbase + 16 + r16) * 144 + ka);
        mma_bf16(acc[0][0], a0, b0[0], b0[2]);
        mma_bf16(acc[0][1], a0, b0[1], b0[3]);
        mma_bf16(acc[0][2], a0, b1[0], b1[2]);
        mma_bf16(acc[0][3], a0, b1[1], b1[3]);
        mma_bf16(acc[1][0], a1, b0[0], b0[2]);
        mma_bf16(acc[1][1], a1, b0[1], b0[3]);
        mma_bf16(acc[1][2], a1, b1[0], b1[2]);
        mma_bf16(acc[1][3], a1, b1[1], b1[3]);
    }
}

// A row-major, B row-major [k][n] loaded via ldmatrix.trans (for P @ V)
__device__ __forceinline__ void gemm_pass_tb(float acc[2][4][4], uint32_t aBase,
                                             uint32_t bBase, int mbase, int nbase,
                                             int lane) {
    const int r16 = lane & 15;
    const uint32_t kaq = (lane >> 4) * 16;
    const int krow = ((lane >> 4) << 3) + (lane & 7);   // 0..15 within k16 tile
    const int nch = ((lane >> 3) & 1) * 8;              // n sub-chunk 0 / 8
    #pragma unroll
    for (int kc = 0; kc < 4; ++kc) {
        uint32_t ka = kaq + kc * 32;
        uint32_t a0[4], a1[4], b0[4], b1[4];
        ldsm4(a0, aBase + (mbase + r16) * 144 + ka);
        ldsm4(a1, aBase + (mbase + 16 + r16) * 144 + ka);
        const uint32_t brow = bBase + (kc * 16 + krow) * 144;
        ldsm4t(b0, brow + (nbase + nch) * 2);
        ldsm4t(b1, brow + (nbase + 16 + nch) * 2);
        mma_bf16(acc[0][0], a0, b0[0], b0[2]);
        mma_bf16(acc[0][1], a0, b0[1], b0[3]);
        mma_bf16(acc[0][2], a0, b1[0], b1[2]);
        mma_bf16(acc[0][3], a0, b1[1], b1[3]);
        mma_bf16(acc[1][0], a1, b0[0], b0[2]);
        mma_bf16(acc[1][1], a1, b0[1], b0[3]);
        mma_bf16(acc[1][2], a1, b1[0], b1[2]);
        mma_bf16(acc[1][3], a1, b1[1], b1[3]);
    }
}

__global__ void __launch_bounds__(128, 3)
attn_kernel(const float* __restrict__ x)
{
    extern __shared__ __nv_bfloat16 sm[];
    __nv_bfloat16* xh = sm;
    __nv_bfloat16* xl = sm + PLANE;
    __nv_bfloat16* Wh = sm + 2 * PLANE;     // Wq / Wv-hi / P-hi
    __nv_bfloat16* Wl = sm + 3 * PLANE;     // Wk / Wv-lo / P-lo
    __nv_bfloat16* Qh = sm + 4 * PLANE;
    __nv_bfloat16* Kh = sm + 5 * PLANE;
    __nv_bfloat16* Vh = sm + 6 * PLANE;     // V row-major [m][d]
    __nv_bfloat16* Vl = sm + 7 * PLANE;
    float* Sc = (float*)sm;                 // scores fp32 [64][65], aliases x

    const int tid = threadIdx.x, lane = tid & 31, wid = tid >> 5;
    const int warp_m = wid >> 1, warp_n = wid & 1;
    const int mbase = warp_m * 32, nbase = warp_n * 32;
    const int lr = lane >> 2, lc = lane & 3;

    const int h = blockIdx.x % NHEADS;
    const int n = blockIdx.x / NHEADS;
    const int b = n >> 6, hb = (n >> 3) & 7, wb = n & 7;

    const uint32_t sb = (uint32_t)__cvta_generic_to_shared(sm);
    const uint32_t sXH = sb, sXL = sb + PLB, sWH = sb + 2 * PLB, sWL = sb + 3 * PLB;
    const uint32_t sQH = sb + 4 * PLB, sKH = sb + 5 * PLB;
    const uint32_t sVH = sb + 6 * PLB, sVL = sb + 7 * PLB;

    // ---- stage x: load fp32 directly, split hi/lo inline, pad rows zero ----
    for (int q = tid; q < 512; q += 128) {
        int l = q >> 3, ch = q & 7;
        uint4 hv = make_uint4(0, 0, 0, 0), lv = make_uint4(0, 0, 0, 0);
        if (l < LW) {
            int i = l / 7, j = l - i * 7;
            const float* src = x + (((size_t)(b * 56 + hb * 7 + i)) * 56 + (wb * 7 + j)) * CCH
                               + h * DH + ch * 8;
            float4 f0 = *(const float4*)src;
            float4 f1 = *(const float4*)(src + 4);
            __nv_bfloat16 h0, l0, h1, l1;
            split_bf(f0.x, h0, l0); split_bf(f0.y, h1, l1);
            hv.x = packbf(h0, h1); lv.x = packbf(l0, l1);
            split_bf(f0.z, h0, l0); split_bf(f0.w, h1, l1);
            hv.y = packbf(h0, h1); lv.y = packbf(l0, l1);
            split_bf(f1.x, h0, l0); split_bf(f1.y, h1, l1);
            hv.z = packbf(h0, h1); lv.z = packbf(l0, l1);
            split_bf(f1.z, h0, l0); split_bf(f1.w, h1, l1);
            hv.w = packbf(h0, h1); lv.w = packbf(l0, l1);
        }
        *(uint4*)(xh + l * STBF + ch * 8) = hv;
        *(uint4*)(xl + l * STBF + ch * 8) = lv;
    }
    for (int q = tid; q < 1024; q += 128) {
        int p = q >> 9, rem = q & 511, e = rem >> 3, ch = rem & 7;
        *(uint4*)((p ? Wl : Wh) + e * STBF + ch * 8) =
            *(const uint4*)((p ? g_wkh : g_wqh) + h * 4096 + e * 64 + ch * 8);
    }
    __syncthreads();

    // ---- merged Q & K projections: shared A fragments, one phase ----
    {
        float aq[2][4][4] = {}, ak[2][4][4] = {};
        const int r16 = lane & 15;
        const uint32_t kaq = (lane >> 4) * 16;
        #pragma unroll
        for (int kc = 0; kc < 4; ++kc) {
            uint32_t ka = kaq + kc * 32;
            uint32_t a0[4], a1[4], bq0[4], bq1[4], bk0[4], bk1[4];
            ldsm4(a0, sXH + (mbase + r16) * 144 + ka);
            ldsm4(a1, sXH + (mbase + 16 + r16) * 144 + ka);
            ldsm4(bq0, sWH + (nbase + r16) * 144 + ka);
            ldsm4(bq1, sWH + (nbase + 16 + r16) * 144 + ka);
            ldsm4(bk0, sWL + (nbase + r16) * 144 + ka);
            ldsm4(bk1, sWL + (nbase + 16 + r16) * 144 + ka);
            mma_bf16(aq[0][0], a0, bq0[0], bq0[2]);
            mma_bf16(aq[0][1], a0, bq0[1], bq0[3]);
            mma_bf16(aq[0][2], a0, bq1[0], bq1[2]);
            mma_bf16(aq[0][3], a0, bq1[1], bq1[3]);
            mma_bf16(aq[1][0], a1, bq0[0], bq0[2]);
            mma_bf16(aq[1][1], a1, bq0[1], bq0[3]);
            mma_bf16(aq[1][2], a1, bq1[0], bq1[2]);
            mma_bf16(aq[1][3], a1, bq1[1], bq1[3]);
            mma_bf16(ak[0][0], a0, bk0[0], bk0[2]);
            mma_bf16(ak[0][1], a0, bk0[1], bk0[3]);
            mma_bf16(ak[0][2], a0, bk1[0], bk1[2]);
            mma_bf16(ak[0][3], a0, bk1[1], bk1[3]);
            mma_bf16(ak[1][0], a1, bk0[0], bk0[2]);
            mma_bf16(ak[1][1], a1, bk0[1], bk0[3]);
            mma_bf16(ak[1][2], a1, bk1[0], bk1[2]);
            mma_bf16(ak[1][3], a1, bk1[1], bk1[3]);
        }
        uint32_t* OQ = (uint32_t*)Qh;
        uint32_t* OK = (uint32_t*)Kh;
        #pragma unroll
        for (int f = 0; f < 2; ++f)
            #pragma unroll
            for (int g = 0; g < 4; ++g) {
                int r = mbase + 16 * f + lr;
                int w = r * 36 + (nbase + 8 * g) / 2 + lc;
                OQ[w] = packbf(__float2bfloat16(aq[f][g][0]), __float2bfloat16(aq[f][g][1]));
                OQ[w + 8 * 36] = packbf(__float2bfloat16(aq[f][g][2]), __float2bfloat16(aq[f][g][3]));
                OK[w] = packbf(__float2bfloat16(ak[f][g][0]), __float2bfloat16(ak[f][g][1]));
                OK[w + 8 * 36] = packbf(__float2bfloat16(ak[f][g][2]), __float2bfloat16(ak[f][g][3]));
            }
    }
    __syncthreads();

    // ---- V = x @ Wv (3-term split), stored ROW-MAJOR hi/lo (vectorized) ----
    for (int q = tid; q < 1024; q += 128) {
        int p = q >> 9, rem = q & 511, e = rem >> 3, ch = rem & 7;
        *(uint4*)((p ? Wl : Wh) + e * STBF + ch * 8) =
            *(const uint4*)((p ? g_wvl : g_wvh) + h * 4096 + e * 64 + ch * 8);
    }
    __syncthreads();
    {
        float acc[2][4][4] = {};
        gemm_pass(acc, sXH, sWH, mbase, nbase, lane);
        gemm_pass(acc, sXH, sWL, mbase, nbase, lane);
        gemm_pass(acc, sXL, sWH, mbase, nbase, lane);
        uint32_t* OVH = (uint32_t*)Vh;
        uint32_t* OVL = (uint32_t*)Vl;
        #pragma unroll
        for (int f = 0; f < 2; ++f)
            #pragma unroll
            for (int g = 0; g < 4; ++g) {
                int r = mbase + 16 * f + lr;
                int w = r * 36 + (nbase + 8 * g) / 2 + lc;
                __nv_bfloat16 h0, l0, h1, l1;
                split_bf(acc[f][g][0], h0, l0);
                split_bf(acc[f][g][1], h1, l1);
                OVH[w] = packbf(h0, h1);
                OVL[w] = packbf(l0, l1);
                split_bf(acc[f][g][2], h0, l0);
                split_bf(acc[f][g][3], h1, l1);
                OVH[w + 8 * 36] = packbf(h0, h1);
                OVL[w + 8 * 36] = packbf(l0, l1);
            }
    }
    __syncthreads();

    // ---- scores = Qh @ Kh^T, scale + mask -> Sc (aliases x planes) ----
    {
        float acc[2][4][4] = {};
        gemm_pass(acc, sQH, sKH, mbase, nbase, lane);
        #pragma unroll
        for (int f = 0; f < 2; ++f)
            #pragma unroll
            for (int g = 0; g < 4; ++g) {
                int r = mbase + 16 * f + lr;
                int c = nbase + 8 * g + 2 * lc;
                Sc[r * SCST + c]           = (c     < LW) ? acc[f][g][0] * 0.125f : -1e30f;
                Sc[r * SCST + c + 1]       = (c + 1 < LW) ? acc[f][g][1] * 0.125f : -1e30f;
                Sc[(r + 8) * SCST + c]     = (c     < LW) ? acc[f][g][2] * 0.125f : -1e30f;
                Sc[(r + 8) * SCST + c + 1] = (c + 1 < LW) ? acc[f][g][3] * 0.125f : -1e30f;
            }
    }
    __syncthreads();

    // ---- softmax rows 0..48, write P hi/lo (aliases W planes) ----
    if (tid < LW) {
        float* row = Sc + tid * SCST;
        float mx = -1e30f;
        #pragma unroll
        for (int m = 0; m < LW; ++m) mx = fmaxf(mx, row[m]);
        float s = 0.f;
        #pragma unroll
        for (int m = 0; m < LW; ++m) { float e = __expf(row[m] - mx); row[m] = e; s += e; }
        float inv = 1.f / s;
        uint32_t* ph = (uint32_t*)(Wh + tid * STBF);
        uint32_t* pl = (uint32_t*)(Wl + tid * STBF);
        #pragma unroll
        for (int mw = 0; mw < 32; ++mw) {
            int m0 = 2 * mw;
            float p0 = (m0     < LW) ? row[m0] * inv     : 0.f;
            float p1 = (m0 + 1 < LW) ? row[m0 + 1] * inv : 0.f;
            __nv_bfloat16 h0, l0, h1, l1;
            split_bf(p0, h0, l0);
            split_bf(p1, h1, l1);
            ph[mw] = packbf(h0, h1);
            pl[mw] = packbf(l0, l1);
        }
    }
    __syncthreads();

    // ---- out = P @ V (3-term, trans-B ldsm), store split bf16 ----
    {
        float acc[2][4][4] = {};
        gemm_pass_tb(acc, sWH, sVH, mbase, nbase, lane);
        gemm_pass_tb(acc, sWH, sVL, mbase, nbase, lane);
        gemm_pass_tb(acc, sWL, sVH, mbase, nbase, lane);
        #pragma unroll
        for (int f = 0; f < 2; ++f)
            #pragma unroll
            for (int g = 0; g < 4; ++g) {
                int r = mbase + 16 * f + lr;
                int c = nbase + 8 * g + 2 * lc;
                __nv_bfloat16 h0, l0, h1, l1;
                if (r < LW) {
                    size_t off = ((size_t)n * LW + r) * CCH + h * DH + c;
                    split_bf(acc[f][g][0], h0, l0);
                    split_bf(acc[f][g][1], h1, l1);
                    *(uint32_t*)(g_sh + off) = packbf(h0, h1);
                    *(uint32_t*)(g_sl + off) = packbf(l0, l1);
                }
                if (r + 8 < LW) {
                    size_t off = ((size_t)n * LW + r + 8) * CCH + h * DH + c;
                    split_bf(acc[f][g][2], h0, l0);
                    split_bf(acc[f][g][3], h1, l1);
                    *(uint32_t*)(g_sh + off) = packbf(h0, h1);
                    *(uint32_t*)(g_sl + off) = packbf(l0, l1);
                }
            }
    }
}

// ============================================================================
// Kernel B: y = S @ Wo^T + bo, bf16x3, 3-stage cp.async pipeline, SWIZZLED
// unpadded 64B rows. Block 128x64, BK=32, 256 threads.
// ============================================================================
#define PSTG 24576                     // bytes per stage
#define QAH  0
#define QAL  8192
#define QBH  16384
#define QBL  20480
#define PROJ_SMEM (3 * PSTG)           // 73728 B

__device__ __forceinline__ uint32_t swr(int row, int ch) {
    return (uint32_t)(row * 64 + ((ch ^ ((row >> 1) & 3)) << 4));
}

__device__ __forceinline__ void proj_stage(uint32_t sb, int s, int kt,
                                           int m_base, int n_base, int tid) {
    const uint32_t base = sb + s * PSTG;
    #pragma unroll
    for (int c = tid; c < 1024; c += 256) {
        int p = c >> 9, rem = c & 511, row = rem >> 2, ch = rem & 3;
        const __nv_bfloat16* src =
            (p ? g_sl : g_sh) + (size_t)(m_base + row) * CCH + kt + ch * 8;
        cpa16(base + (p ? QAL : QAH) + swr(row, ch), src);
    }
    #pragma unroll
    for (int c = tid; c < 512; c += 256) {
        int p = c >> 8, rem = c & 255, row = rem >> 2, ch = rem & 3;
        const __nv_bfloat16* src =
            (p ? g_wol : g_woh) + (size_t)(n_base + row) * CCH + kt + ch * 8;
        cpa16(base + (p ? QBL : QBH) + swr(row, ch), src);
    }
    cpa_commit();
}

__global__ void __launch_bounds__(256, 3)
proj_kernel(const float* __restrict__ bo, float* __restrict__ y)
{
    extern __shared__ __nv_bfloat16 psm[];
    const int tid = threadIdx.x, lane = tid & 31, wid = tid >> 5;
    const int warp_m = wid >> 1, warp_n = wid & 1;
    const int lr = lane >> 2, lc = lane & 3;
    const int n_base = (blockIdx.x % 12) * 64;
    const int m_base = (blockIdx.x / 12) * 128;
    const uint32_t sb = (uint32_t)__cvta_generic_to_shared(psm);
    const int r16 = lane & 15;
    const int colq = (lane >> 4);

    float acc[2][4][4] = {};

    auto compute = [&](int s) {
        const uint32_t base = sb + s * PSTG;
        const uint32_t aH = base + QAH, aL = base + QAL;
        const uint32_t bH = base + QBH, bL = base + QBL;
        #pragma unroll
        for (int kc = 0; kc < 2; ++kc) {
            const int ch = colq + kc * 2;
            const int ra0 = warp_m * 32 + r16, ra1 = ra0 + 16;
            const int rb0 = warp_n * 32 + r16, rb1 = rb0 + 16;
            uint32_t ah0[4], ah1[4], al0[4], al1[4], bh0[4], bh1[4], bl0[4], bl1[4];
            ldsm4(ah0, aH + swr(ra0, ch));
            ldsm4(ah1, aH + swr(ra1, ch));
            ldsm4(al0, aL + swr(ra0, ch));
            ldsm4(al1, aL + swr(ra1, ch));
            ldsm4(bh0, bH + swr(rb0, ch));
            ldsm4(bh1, bH + swr(rb1, ch));
            ldsm4(bl0, bL + swr(rb0, ch));
            ldsm4(bl1, bL + swr(rb1, ch));
            mma_bf16(acc[0][0], ah0, bh0[0], bh0[2]);
            mma_bf16(acc[0][0], ah0, bl0[0], bl0[2]);
            mma_bf16(acc[0][0], al0, bh0[0], bh0[2]);
            mma_bf16(acc[0][1], ah0, bh0[1], bh0[3]);
            mma_bf16(acc[0][1], ah0, bl0[1], bl0[3]);
            mma_bf16(acc[0][1], al0, bh0[1], bh0[3]);
            mma_bf16(acc[0][2], ah0, bh1[0], bh1[2]);
            mma_bf16(acc[0][2], ah0, bl1[0], bl1[2]);
            mma_bf16(acc[0][2], al0, bh1[0], bh1[2]);
            mma_bf16(acc[0][3], ah0, bh1[1], bh1[3]);
            mma_bf16(acc[0][3], ah0, bl1[1], bl1[3]);
            mma_bf16(acc[0][3], al0, bh1[1], bh1[3]);
            mma_bf16(acc[1][0], ah1, bh0[0], bh0[2]);
            mma_bf16(acc[1][0], ah1, bl0[0], bl0[2]);
            mma_bf16(acc[1][0], al1, bh0[0], bh0[2]);
            mma_bf16(acc[1][1], ah1, bh0[1], bh0[3]);
            mma_bf16(acc[1][1], ah1, bl0[1], bl0[3]);
            mma_bf16(acc[1][1], al1, bh0[1], bh0[3]);
            mma_bf16(acc[1][2], ah1, bh1[0], bh1[2]);
            mma_bf16(acc[1][2], ah1, bl1[0], bl1[2]);
            mma_bf16(acc[1][2], al1, bh1[0], bh1[2]);
            mma_bf16(acc[1][3], ah1, bh1[1], bh1[3]);
            mma_bf16(acc[1][3], ah1, bl1[1], bl1[3]);
            mma_bf16(acc[1][3], al1, bh1[1], bh1[3]);
        }
    };

    proj_stage(sb, 0, 0, m_base, n_base, tid);
    proj_stage(sb, 1, 32, m_base, n_base, tid);
    #pragma unroll 1
    for (int t = 0; t < 24; ++t) {
        if (t < 23) cpa_wait<1>(); else cpa_wait<0>();
        __syncthreads();
        compute(t % 3);
        if (t + 2 < 24) proj_stage(sb, (t + 2) % 3, (t + 2) * 32, m_base, n_base, tid);
    }

    #pragma unroll
    for (int g = 0; g < 4; ++g) {
        int c = n_base + warp_n * 32 + 8 * g + 2 * lc;
        float b0 = bo[c], b1 = bo[c + 1];
        #pragma unroll
        for (int f = 0; f < 2; ++f) {
            int r = m_base + warp_m * 32 + 16 * f + lr;
            *(float2*)&y[(size_t)r * CCH + c] =
                make_float2(acc[f][g][0] + b0, acc[f][g][1] + b1);
            *(float2*)&y[(size_t)(r + 8) * CCH + c] =
                make_float2(acc[f][g][2] + b0, acc[f][g][3] + b1);
        }
    }
}

// ============================================================================
extern "C" void kernel_launch(void* const* d_in, const int* in_sizes, int n_in,
                              void* d_out, int out_size)
{
    const float* x  = (const float*)d_in[0];
    const float* Wq = (const float*)d_in[1];
    const float* Wk = (const float*)d_in[2];
    const float* Wv = (const float*)d_in[3];
    const float* Wo = (const float*)d_in[4];
    const float* bo = (const float*)d_in[5];
    float* y = (float*)d_out;

    cudaFuncSetAttribute(attn_kernel, cudaFuncAttributeMaxDynamicSharedMemorySize, SMEMB);
    cudaFuncSetAttribute(proj_kernel, cudaFuncAttributeMaxDynamicSharedMemorySize, PROJ_SMEM);

    split_w_kernel<<<576, 256>>>(Wq, Wk, Wv, Wo);
    attn_kernel<<<NWIN * NHEADS, 128, SMEMB>>>(x);
    proj_kernel<<<784 * 12, 256, PROJ_SMEM>>>(bo, y);
}